// round 1
// baseline (speedup 1.0000x reference)
#include <cuda_runtime.h>

// FoRefLoss: sum over B rows of (dx^2 + dy^2 + wrapped_angle^2)
//   angle = (pred[:,2]-label[:,2]) * 2*pi, clamped to [0,pi], divided by pi.
// B = 8388608, inputs [B,3] fp32 row-major. Output: 1 fp32 scalar.

#define NBLOCKS 1184
#define NTHREADS 256

__device__ float g_partials[NBLOCKS];

__device__ __forceinline__ float angle_term(float p, float l) {
    const float TWO_PI     = 6.283185307179586f;
    const float INV_TWO_PI = 0.15915494309189535f;
    const float INV_PI     = 0.3183098861837907f;
    float d = (p - l) * TWO_PI;
    float a = fabsf(d);
    // range-reduce to [0, 2pi) without fmodf's division sequence
    a = fmaf(-floorf(a * INV_TWO_PI), TWO_PI, a);
    // clamp_angle: fold [pi, 2pi) -> (0, pi]
    float c = fminf(a, TWO_PI - a);
    float t = c * INV_PI;
    return t * t;
}

__global__ void __launch_bounds__(NTHREADS)
foref_loss_kernel(const float4* __restrict__ pred,
                  const float4* __restrict__ lab,
                  int n_groups) // groups of 4 rows = 3 float4s
{
    float sum = 0.0f;
    int stride = gridDim.x * blockDim.x;
    for (int g = blockIdx.x * blockDim.x + threadIdx.x; g < n_groups; g += stride) {
        int base = g * 3;
        float4 p0 = pred[base + 0];
        float4 p1 = pred[base + 1];
        float4 p2 = pred[base + 2];
        float4 l0 = lab[base + 0];
        float4 l1 = lab[base + 1];
        float4 l2 = lab[base + 2];

        float d;
        // row 0: p0.x p0.y | p0.z(theta)
        d = p0.x - l0.x; sum = fmaf(d, d, sum);
        d = p0.y - l0.y; sum = fmaf(d, d, sum);
        sum += angle_term(p0.z, l0.z);
        // row 1: p0.w p1.x | p1.y(theta)
        d = p0.w - l0.w; sum = fmaf(d, d, sum);
        d = p1.x - l1.x; sum = fmaf(d, d, sum);
        sum += angle_term(p1.y, l1.y);
        // row 2: p1.z p1.w | p2.x(theta)
        d = p1.z - l1.z; sum = fmaf(d, d, sum);
        d = p1.w - l1.w; sum = fmaf(d, d, sum);
        sum += angle_term(p2.x, l2.x);
        // row 3: p2.y p2.z | p2.w(theta)
        d = p2.y - l2.y; sum = fmaf(d, d, sum);
        d = p2.z - l2.z; sum = fmaf(d, d, sum);
        sum += angle_term(p2.w, l2.w);
    }

    // warp reduce
    #pragma unroll
    for (int off = 16; off > 0; off >>= 1)
        sum += __shfl_down_sync(0xFFFFFFFFu, sum, off);

    __shared__ float smem[NTHREADS / 32];
    int lane = threadIdx.x & 31;
    int wid  = threadIdx.x >> 5;
    if (lane == 0) smem[wid] = sum;
    __syncthreads();

    if (wid == 0) {
        float v = (lane < NTHREADS / 32) ? smem[lane] : 0.0f;
        #pragma unroll
        for (int off = 4; off > 0; off >>= 1)
            v += __shfl_down_sync(0xFFFFFFFFu, v, off);
        if (lane == 0) g_partials[blockIdx.x] = v;
    }
}

__global__ void __launch_bounds__(1024)
foref_finalize_kernel(float* __restrict__ out)
{
    float v = 0.0f;
    for (int i = threadIdx.x; i < NBLOCKS; i += blockDim.x)
        v += g_partials[i];

    #pragma unroll
    for (int off = 16; off > 0; off >>= 1)
        v += __shfl_down_sync(0xFFFFFFFFu, v, off);

    __shared__ float smem[32];
    int lane = threadIdx.x & 31;
    int wid  = threadIdx.x >> 5;
    if (lane == 0) smem[wid] = v;
    __syncthreads();

    if (wid == 0) {
        float t = (lane < 32) ? smem[lane] : 0.0f;
        #pragma unroll
        for (int off = 16; off > 0; off >>= 1)
            t += __shfl_down_sync(0xFFFFFFFFu, t, off);
        if (lane == 0) out[0] = t;
    }
}

extern "C" void kernel_launch(void* const* d_in, const int* in_sizes, int n_in,
                              void* d_out, int out_size)
{
    const float4* pred = (const float4*)d_in[0];
    const float4* lab  = (const float4*)d_in[1];
    float* out = (float*)d_out;

    int n_floats = in_sizes[0];        // 25165824
    int n_groups = n_floats / 12;      // 2097152 (exact; 4 rows per group)

    foref_loss_kernel<<<NBLOCKS, NTHREADS>>>(pred, lab, n_groups);
    foref_finalize_kernel<<<1, 1024>>>(out);
}

// round 2
// speedup vs baseline: 1.0009x; 1.0009x over previous
#include <cuda_runtime.h>

// FoRefLoss: sum over B rows of (dx^2 + dy^2 + wrapped_angle^2)
//   angle = (pred[:,2]-label[:,2]) * 2*pi, clamped to [0,pi], divided by pi.
// B = 8388608, inputs [B,3] fp32 row-major. Output: 1 fp32 scalar.
// Single-kernel: last block to arrive performs the final reduction
// (fixed summation order -> deterministic across replays).

#define NBLOCKS 1184
#define NTHREADS 256

__device__ float g_partials[NBLOCKS];
__device__ unsigned int g_arrived = 0;

__device__ __forceinline__ float angle_term(float p, float l) {
    const float TWO_PI     = 6.283185307179586f;
    const float INV_TWO_PI = 0.15915494309189535f;
    const float INV_PI     = 0.3183098861837907f;
    float d = (p - l) * TWO_PI;
    float a = fabsf(d);
    // range-reduce to [0, 2pi) without fmodf's division sequence
    a = fmaf(-floorf(a * INV_TWO_PI), TWO_PI, a);
    // clamp_angle: fold [pi, 2pi) -> (0, pi]
    float c = fminf(a, TWO_PI - a);
    float t = c * INV_PI;
    return t * t;
}

__device__ __forceinline__ float4 ldcs4(const float4* p) {
    return __ldcs(p);
}

__global__ void __launch_bounds__(NTHREADS)
foref_loss_kernel(const float4* __restrict__ pred,
                  const float4* __restrict__ lab,
                  int n_groups,  // groups of 4 rows = 3 float4s
                  float* __restrict__ out)
{
    float sum = 0.0f;
    int stride = gridDim.x * blockDim.x;
    for (int g = blockIdx.x * blockDim.x + threadIdx.x; g < n_groups; g += stride) {
        int base = g * 3;
        float4 p0 = ldcs4(pred + base + 0);
        float4 p1 = ldcs4(pred + base + 1);
        float4 p2 = ldcs4(pred + base + 2);
        float4 l0 = ldcs4(lab  + base + 0);
        float4 l1 = ldcs4(lab  + base + 1);
        float4 l2 = ldcs4(lab  + base + 2);

        float d;
        // row 0: p0.x p0.y | p0.z(theta)
        d = p0.x - l0.x; sum = fmaf(d, d, sum);
        d = p0.y - l0.y; sum = fmaf(d, d, sum);
        sum += angle_term(p0.z, l0.z);
        // row 1: p0.w p1.x | p1.y(theta)
        d = p0.w - l0.w; sum = fmaf(d, d, sum);
        d = p1.x - l1.x; sum = fmaf(d, d, sum);
        sum += angle_term(p1.y, l1.y);
        // row 2: p1.z p1.w | p2.x(theta)
        d = p1.z - l1.z; sum = fmaf(d, d, sum);
        d = p1.w - l1.w; sum = fmaf(d, d, sum);
        sum += angle_term(p2.x, l2.x);
        // row 3: p2.y p2.z | p2.w(theta)
        d = p2.y - l2.y; sum = fmaf(d, d, sum);
        d = p2.z - l2.z; sum = fmaf(d, d, sum);
        sum += angle_term(p2.w, l2.w);
    }

    // intra-block reduce
    #pragma unroll
    for (int off = 16; off > 0; off >>= 1)
        sum += __shfl_down_sync(0xFFFFFFFFu, sum, off);

    __shared__ float smem[NTHREADS / 32];
    __shared__ bool is_last;
    int lane = threadIdx.x & 31;
    int wid  = threadIdx.x >> 5;
    if (lane == 0) smem[wid] = sum;
    __syncthreads();

    if (wid == 0) {
        float v = (lane < NTHREADS / 32) ? smem[lane] : 0.0f;
        #pragma unroll
        for (int off = 4; off > 0; off >>= 1)
            v += __shfl_down_sync(0xFFFFFFFFu, v, off);
        if (lane == 0) {
            g_partials[blockIdx.x] = v;
            __threadfence();
            unsigned int t = atomicAdd(&g_arrived, 1u);
            is_last = (t == (unsigned int)(gridDim.x - 1));
        }
    }
    __syncthreads();

    if (is_last) {
        // all partials are globally visible now; reduce in fixed order
        float v = 0.0f;
        for (int i = threadIdx.x; i < NBLOCKS; i += NTHREADS)
            v += g_partials[i];

        #pragma unroll
        for (int off = 16; off > 0; off >>= 1)
            v += __shfl_down_sync(0xFFFFFFFFu, v, off);

        if (lane == 0) smem[wid] = v;
        __syncthreads();

        if (wid == 0) {
            float t2 = (lane < NTHREADS / 32) ? smem[lane] : 0.0f;
            #pragma unroll
            for (int off = 4; off > 0; off >>= 1)
                t2 += __shfl_down_sync(0xFFFFFFFFu, t2, off);
            if (lane == 0) {
                out[0] = t2;
                g_arrived = 0;  // reset for next graph replay
            }
        }
    }
}

extern "C" void kernel_launch(void* const* d_in, const int* in_sizes, int n_in,
                              void* d_out, int out_size)
{
    const float4* pred = (const float4*)d_in[0];
    const float4* lab  = (const float4*)d_in[1];
    float* out = (float*)d_out;

    int n_floats = in_sizes[0];        // 25165824
    int n_groups = n_floats / 12;      // 2097152 (exact; 4 rows per group)

    foref_loss_kernel<<<NBLOCKS, NTHREADS>>>(pred, lab, n_groups, out);
}

// round 3
// speedup vs baseline: 1.0589x; 1.0580x over previous
#include <cuda_runtime.h>

// FoRefLoss: sum over B rows of (dx^2 + dy^2 + wrapped_angle^2), B=8388608.
// Coalesced variant: each thread handles one float4 per step at lane-consecutive
// indices. Component c of float4 k is the angle component iff (k+c) % 3 == 2.
// Angle term in turn-space: t = 2*min(frac(|d|), 1-frac(|d|)), contribution t^2.
// Single kernel; last-arriving block reduces partials in fixed order.

#define NBLOCKS 1024
#define NTHREADS 256

__device__ float g_partials[NBLOCKS];
__device__ unsigned int g_arrived = 0;

__device__ __forceinline__ float vcomp(float p, float l, bool is_angle) {
    float d = p - l;              // difference in "turns" (full circle = 1.0)
    float ad = fabsf(d);
    float f = ad - floorf(ad);    // frac in [0,1)
    float w = fminf(f, 1.0f - f); // folded to [0, 0.5]
    return is_angle ? (w + w) : d; // angle: 2w = clamped_angle/pi; else plain diff
}

__global__ void __launch_bounds__(NTHREADS)
foref_loss_kernel(const float4* __restrict__ pred,
                  const float4* __restrict__ lab,
                  int n4,                 // total float4 count per tensor
                  float* __restrict__ out)
{
    const int stride = NBLOCKS * NTHREADS;      // 262144; 262144 % 3 == 1
    int tid0 = blockIdx.x * NTHREADS + threadIdx.x;

    float sum = 0.0f;
    int iters = n4 / stride;

    int k = tid0;
    int m = k % 3;

    #pragma unroll 2
    for (int it = 0; it < iters; ++it) {
        float4 p = pred[k];
        float4 l = lab[k];
        // component c is angle iff (k + c) % 3 == 2
        bool aA = (m == 2);   // c = 0 and c = 3
        bool aB = (m == 1);   // c = 1
        bool aC = (m == 0);   // c = 2
        float v;
        v = vcomp(p.x, l.x, aA); sum = fmaf(v, v, sum);
        v = vcomp(p.y, l.y, aB); sum = fmaf(v, v, sum);
        v = vcomp(p.z, l.z, aC); sum = fmaf(v, v, sum);
        v = vcomp(p.w, l.w, aA); sum = fmaf(v, v, sum);
        k += stride;
        m = (m == 2) ? 0 : (m + 1);   // stride % 3 == 1
    }
    // generic tail (empty for n4 = 6291456)
    if (k < n4) {
        float4 p = pred[k];
        float4 l = lab[k];
        bool aA = (m == 2), aB = (m == 1), aC = (m == 0);
        float v;
        v = vcomp(p.x, l.x, aA); sum = fmaf(v, v, sum);
        v = vcomp(p.y, l.y, aB); sum = fmaf(v, v, sum);
        v = vcomp(p.z, l.z, aC); sum = fmaf(v, v, sum);
        v = vcomp(p.w, l.w, aA); sum = fmaf(v, v, sum);
    }

    // intra-block reduce
    #pragma unroll
    for (int off = 16; off > 0; off >>= 1)
        sum += __shfl_down_sync(0xFFFFFFFFu, sum, off);

    __shared__ float smem[NTHREADS / 32];
    __shared__ bool is_last;
    int lane = threadIdx.x & 31;
    int wid  = threadIdx.x >> 5;
    if (lane == 0) smem[wid] = sum;
    __syncthreads();

    if (wid == 0) {
        float v = (lane < NTHREADS / 32) ? smem[lane] : 0.0f;
        #pragma unroll
        for (int off = 4; off > 0; off >>= 1)
            v += __shfl_down_sync(0xFFFFFFFFu, v, off);
        if (lane == 0) {
            g_partials[blockIdx.x] = v;
            __threadfence();
            unsigned int t = atomicAdd(&g_arrived, 1u);
            is_last = (t == (unsigned int)(gridDim.x - 1));
        }
    }
    __syncthreads();

    if (is_last) {
        float v = 0.0f;
        for (int i = threadIdx.x; i < NBLOCKS; i += NTHREADS)
            v += g_partials[i];

        #pragma unroll
        for (int off = 16; off > 0; off >>= 1)
            v += __shfl_down_sync(0xFFFFFFFFu, v, off);

        if (lane == 0) smem[wid] = v;
        __syncthreads();

        if (wid == 0) {
            float t2 = (lane < NTHREADS / 32) ? smem[lane] : 0.0f;
            #pragma unroll
            for (int off = 4; off > 0; off >>= 1)
                t2 += __shfl_down_sync(0xFFFFFFFFu, t2, off);
            if (lane == 0) {
                out[0] = t2;
                g_arrived = 0;  // reset for next graph replay
            }
        }
    }
}

extern "C" void kernel_launch(void* const* d_in, const int* in_sizes, int n_in,
                              void* d_out, int out_size)
{
    const float4* pred = (const float4*)d_in[0];
    const float4* lab  = (const float4*)d_in[1];
    float* out = (float*)d_out;

    int n_floats = in_sizes[0];   // 25165824
    int n4 = n_floats / 4;        // 6291456

    foref_loss_kernel<<<NBLOCKS, NTHREADS>>>(pred, lab, n4, out);
}